// round 8
// baseline (speedup 1.0000x reference)
#include <cuda_runtime.h>
#include <math.h>

#define HN 320
#define NPLANE (HN*HN)
#define NB 16
#define NTOT (NB*2*NPLANE)
#define LPC 4
#define FTH 128
#define GRPS (HN/LPC)
#define FGRID (NB*GRPS)          // 1280
#define LAM_TV 0.005f
#define LAM_W  0.005f
#define INV_S2 0.70710678118654752f

__device__ float  g_Z[NTOT];
__device__ float  g_X[NTOT];
__device__ float  g_T1[NTOT];            // planar z_step
__device__ float2 g_T1c[NB*NPLANE];      // complex temp
__device__ float2 g_T2c[NB*NPLANE];      // complex temp
__device__ float2 g_ykc[NB*NPLANE];      // D*mask*y, transposed
__device__ float  g_mT[NB*NPLANE];       // mask, transposed
__device__ float2 g_tw[HN];

// ---------------- twiddles ----------------
__global__ void k_tw() {
    int k = threadIdx.x;
    if (k < HN) {
        double a = -2.0 * 3.14159265358979323846 * (double)k / (double)HN;
        g_tw[k] = make_float2((float)cos(a), (float)sin(a));
    }
}

// ---------------- prep ----------------
__global__ void __launch_bounds__(256) k_prep(const float* __restrict__ y,
                                              const float* __restrict__ mask) {
    __shared__ float sm[32][33], s0[32][33], s1[32][33];
    int b = blockIdx.x / 100, t = blockIdx.x % 100;
    int h0 = (t / 10) * 32, w0 = (t % 10) * 32;
    for (int i = threadIdx.x; i < 1024; i += 256) {
        int r = i >> 5, c = i & 31;
        sm[r][c] = mask[b*NPLANE + (h0+r)*HN + w0+c];
        s0[r][c] = y[(b*2+0)*NPLANE + (h0+r)*HN + w0+c];
        s1[r][c] = y[(b*2+1)*NPLANE + (h0+r)*HN + w0+c];
    }
    __syncthreads();
    for (int i = threadIdx.x; i < 1024; i += 256) {
        int ww = i >> 5, hh = i & 31;
        float sg = (((h0+hh) + (w0+ww)) & 1) ? -1.f : 1.f;
        float m = sm[hh][ww];
        int o = (w0+ww)*HN + h0+hh;
        g_mT[b*NPLANE + o] = m;
        g_ykc[b*NPLANE + o] = make_float2(sg*m*s0[hh][ww], sg*m*s1[hh][ww]);
    }
}

// ---------------- register/shuffle 320-pt FFT: 320 = 32(lanes) x 10(slots) ----------------
__device__ __forceinline__ float2 cmul(float2 a, float2 b) {
    return make_float2(a.x*b.x - a.y*b.y, a.x*b.y + a.y*b.x);
}

__device__ __forceinline__ void dft5(float2* v, float d) {
    const float c1 = 0.30901699437494742f, c2 = -0.80901699437494745f;
    const float s1 = 0.95105651629515353f, s2 = 0.58778525229247312f;
    float t1r=v[1].x+v[4].x, t1i=v[1].y+v[4].y;
    float t2r=v[2].x+v[3].x, t2i=v[2].y+v[3].y;
    float t3r=v[1].x-v[4].x, t3i=v[1].y-v[4].y;
    float t4r=v[2].x-v[3].x, t4i=v[2].y-v[3].y;
    float v0r=v[0].x, v0i=v[0].y;
    v[0] = make_float2(v0r+t1r+t2r, v0i+t1i+t2i);
    float a1r=v0r+c1*t1r+c2*t2r, a1i=v0i+c1*t1i+c2*t2i;
    float b1r=s1*t3r+s2*t4r,     b1i=s1*t3i+s2*t4i;
    float a2r=v0r+c2*t1r+c1*t2r, a2i=v0i+c2*t1i+c1*t2i;
    float b2r=s2*t3r-s1*t4r,     b2i=s2*t3i-s1*t4i;
    v[1] = make_float2(a1r + d*b1i, a1i - d*b1r);
    v[2] = make_float2(a2r + d*b2i, a2i - d*b2r);
    v[3] = make_float2(a2r - d*b2i, a2i + d*b2r);
    v[4] = make_float2(a1r - d*b1i, a1i + d*b1r);
}

__device__ __forceinline__ void dft10(float2* x, float d) {
    float2 E[5], O[5];
#pragma unroll
    for (int j = 0; j < 5; j++) { E[j] = x[2*j]; O[j] = x[2*j+1]; }
    dft5(E, d); dft5(O, d);
    const float C10[5] = {1.f, 0.80901699437494745f, 0.30901699437494742f,
                          -0.30901699437494742f, -0.80901699437494745f};
    const float S10[5] = {0.f, 0.58778525229247312f, 0.95105651629515353f,
                          0.95105651629515353f, 0.58778525229247312f};
#pragma unroll
    for (int k = 0; k < 5; k++) {
        float2 w = make_float2(C10[k], -d*S10[k]);
        float2 t = cmul(w, O[k]);
        x[k]   = make_float2(E[k].x + t.x, E[k].y + t.y);
        x[k+5] = make_float2(E[k].x - t.x, E[k].y - t.y);
    }
}

__device__ __forceinline__ void xfft32_dif(float2* x, const float2* stw, int lane, float d) {
#pragma unroll
    for (int s = 0; s < 5; s++) {
        const int m = 16 >> s;
        bool bot = (lane & m) != 0;
        int e = (lane & (m-1)) * ((16/m) * 10);
        float2 t = stw[e];
        float2 w = bot ? make_float2(t.x, d*t.y) : make_float2(1.f, 0.f);
        float sg = bot ? -1.f : 1.f;
#pragma unroll
        for (int j = 0; j < 10; j++) {
            float orr = __shfl_xor_sync(0xffffffffu, x[j].x, m);
            float oii = __shfl_xor_sync(0xffffffffu, x[j].y, m);
            float tr = orr + sg*x[j].x;
            float ti = oii + sg*x[j].y;
            x[j] = make_float2(tr*w.x - ti*w.y, tr*w.y + ti*w.x);
        }
    }
}

__device__ __forceinline__ void xfft32_dit_inv(float2* x, const float2* stw, int lane) {
#pragma unroll
    for (int s = 0; s < 5; s++) {
        const int m = 1 << s;
        bool bot = (lane & m) != 0;
        int e = (lane & (m-1)) * ((16/m) * 10);
        float2 t = stw[e];
        float2 w = make_float2(t.x, -t.y);
        float sg = bot ? -1.f : 1.f;
#pragma unroll
        for (int j = 0; j < 10; j++) {
            float orr = __shfl_xor_sync(0xffffffffu, x[j].x, m);
            float oii = __shfl_xor_sync(0xffffffffu, x[j].y, m);
            float pr = bot ? x[j].x : orr,  pi = bot ? x[j].y : oii;
            float qr = bot ? orr : x[j].x,  qi = bot ? oii : x[j].y;
            float wpr = pr*w.x - pi*w.y;
            float wpi = pr*w.y + pi*w.x;
            x[j] = make_float2(qr + sg*wpr, qi + sg*wpi);
        }
    }
}

__device__ __forceinline__ int fwd320(float2* x, const float2* stw, int lane, float d) {
    xfft32_dif(x, stw, lane, d);
    int k1 = __brev(lane) >> 27;
#pragma unroll
    for (int j = 1; j < 10; j++) {
        float2 t = stw[j*k1];
        x[j] = cmul(x[j], make_float2(t.x, d*t.y));
    }
    dft10(x, d);
    return k1;
}

__device__ __forceinline__ void inv320(float2* x, const float2* stw, int lane) {
    int k1 = __brev(lane) >> 27;
    dft10(x, -1.f);
#pragma unroll
    for (int j = 1; j < 10; j++) {
        float2 t = stw[j*k1];
        x[j] = cmul(x[j], make_float2(t.x, -t.y));
    }
    xfft32_dit_inv(x, stw, lane);
}

// ---------------- planar -> complex transposed (sign+scale at load) ----------------
__global__ void __launch_bounds__(FTH) k_fft_p2c(const float* __restrict__ src,
                                                 float2* __restrict__ dst,
                                                 float d, float scale) {
    __shared__ float2 stw[HN];
    __shared__ float2 SL[LPC][HN];
    int img = blockIdx.x / GRPS, r0 = (blockIdx.x % GRPS) * LPC;
    for (int i = threadIdx.x; i < HN; i += FTH) stw[i] = g_tw[i];
    __syncthreads();
    int warp = threadIdx.x >> 5, lane = threadIdx.x & 31;
    int r = r0 + warp;
    float2 x[10];
    float sgE = ((r) & 1) ? -scale : scale;
    float sgO = -sgE;
    const float2* sre = (const float2*)(src + (img*2+0)*NPLANE + r*HN + 10*lane);
    const float2* sim = (const float2*)(src + (img*2+1)*NPLANE + r*HN + 10*lane);
#pragma unroll
    for (int j = 0; j < 5; j++) {
        float2 vr = sre[j], vi = sim[j];
        x[2*j]   = make_float2(sgE*vr.x, sgE*vi.x);
        x[2*j+1] = make_float2(sgO*vr.y, sgO*vi.y);
    }
    int k1 = fwd320(x, stw, lane, d);
#pragma unroll
    for (int j = 0; j < 10; j++) SL[warp][32*j + k1] = x[j];
    __syncthreads();
    float2* D = dst + img*NPLANE;
    for (int i = threadIdx.x; i < LPC*HN; i += FTH) {
        int s = i & (LPC-1), k = i >> 2;
        D[k*HN + r0 + s] = SL[s][k];
    }
}

// ---------------- complex -> planar transposed, dual dst (init pass 2) ----------------
__global__ void __launch_bounds__(FTH) k_fft_c2p(const float2* __restrict__ src,
                                                 float* __restrict__ dstA,
                                                 float* __restrict__ dstB,
                                                 float d, float scale) {
    __shared__ float2 stw[HN];
    __shared__ float2 SL[LPC][HN];
    int img = blockIdx.x / GRPS, r0 = (blockIdx.x % GRPS) * LPC;
    for (int i = threadIdx.x; i < HN; i += FTH) stw[i] = g_tw[i];
    __syncthreads();
    int warp = threadIdx.x >> 5, lane = threadIdx.x & 31;
    int r = r0 + warp;
    float2 x[10];
    const float4* S4 = (const float4*)(src + img*NPLANE + r*HN + 10*lane);
#pragma unroll
    for (int j = 0; j < 5; j++) {
        float4 v = S4[j];
        x[2*j]   = make_float2(v.x, v.y);
        x[2*j+1] = make_float2(v.z, v.w);
    }
    int k1 = fwd320(x, stw, lane, d);
#pragma unroll
    for (int j = 0; j < 10; j++) SL[warp][32*j + k1] = x[j];
    __syncthreads();
    for (int i = threadIdx.x; i < LPC*HN; i += FTH) {
        int s = i & (LPC-1), k = i >> 2;
        float sg = ((k + r0 + s) & 1) ? -scale : scale;
        float2 v = SL[s][k];
        int o = k*HN + r0 + s;
        dstA[(img*2+0)*NPLANE + o] = sg*v.x;
        dstA[(img*2+1)*NPLANE + o] = sg*v.y;
        dstB[(img*2+0)*NPLANE + o] = sg*v.x;
        dstB[(img*2+1)*NPLANE + o] = sg*v.y;
    }
}

// ---------------- fwd col-FFT + mask + inv col-FFT ----------------
__global__ void __launch_bounds__(FTH) k_fft_mid(const float2* __restrict__ src,
                                                 float2* __restrict__ dst) {
    __shared__ float2 stw[HN];
    __shared__ float2 SL[LPC][HN];
    int img = blockIdx.x / GRPS, r0 = (blockIdx.x % GRPS) * LPC;
    for (int i = threadIdx.x; i < HN; i += FTH) stw[i] = g_tw[i];
    __syncthreads();
    int warp = threadIdx.x >> 5, lane = threadIdx.x & 31;
    int r = r0 + warp;
    float2 x[10];
    const float4* S4 = (const float4*)(src + img*NPLANE + r*HN + 10*lane);
#pragma unroll
    for (int j = 0; j < 5; j++) {
        float4 v = S4[j];
        x[2*j]   = make_float2(v.x, v.y);
        x[2*j+1] = make_float2(v.z, v.w);
    }
    int k1 = fwd320(x, stw, lane, 1.f);
    const float*  mrow = g_mT  + img*NPLANE + r*HN;
    const float2* ykr  = g_ykc + img*NPLANE + r*HN;
#pragma unroll
    for (int j = 0; j < 10; j++) {
        int kk = 32*j + k1;
        float m = mrow[kk];
        float2 yk = ykr[kk];
        x[j] = make_float2(x[j].x*m - yk.x, x[j].y*m - yk.y);
    }
    inv320(x, stw, lane);
#pragma unroll
    for (int j = 0; j < 10; j++) SL[warp][10*lane + j] = x[j];
    __syncthreads();
    float2* D = dst + img*NPLANE;
    for (int i = threadIdx.x; i < LPC*HN; i += FTH) {
        int s = i & (LPC-1), k = i >> 2;
        D[k*HN + r0 + s] = SL[s][k];
    }
}

// ---------------- inv row-FFT + fused z_step = z - g ----------------
__global__ void __launch_bounds__(FTH) k_fft_last(const float2* __restrict__ src,
                                                  const float* __restrict__ zin,
                                                  float* __restrict__ zs) {
    __shared__ float2 stw[HN];
    __shared__ float2 SL[LPC][HN];
    int img = blockIdx.x / GRPS, r0 = (blockIdx.x % GRPS) * LPC;
    for (int i = threadIdx.x; i < HN; i += FTH) stw[i] = g_tw[i];
    __syncthreads();
    int warp = threadIdx.x >> 5, lane = threadIdx.x & 31;
    int r = r0 + warp;
    float2 x[10];
    const float4* S4 = (const float4*)(src + img*NPLANE + r*HN + 10*lane);
#pragma unroll
    for (int j = 0; j < 5; j++) {
        float4 v = S4[j];
        x[2*j]   = make_float2(v.x, v.y);
        x[2*j+1] = make_float2(v.z, v.w);
    }
    int k1 = fwd320(x, stw, lane, -1.f);
#pragma unroll
    for (int j = 0; j < 10; j++) SL[warp][32*j + k1] = x[j];
    __syncthreads();
    const float sc = 1.f/320.f;
    for (int i = threadIdx.x; i < LPC*HN; i += FTH) {
        int s = i / HN, w = i - s*HN;
        float sg = (((r0+s) + w) & 1) ? -sc : sc;
        float2 v = SL[s][w];
        int oR = (img*2+0)*NPLANE + (r0+s)*HN + w;
        int oI = (img*2+1)*NPLANE + (r0+s)*HN + w;
        zs[oR] = zin[oR] - sg*v.x;
        zs[oI] = zin[oI] - sg*v.y;
    }
}

// ---------------- warp-parallel 8x32-strip 3-level Haar (r = lane>>2, b = lane&3) ----------------
__device__ __forceinline__ float softt(float v) {
    float m = fabsf(v) - LAM_W;
    return (m > 0.f) ? copysignf(m, v) : 0.f;
}

__device__ __forceinline__ void warp_haar(float a[8], int r, int b) {
    const unsigned FM = 0xffffffffu;
    const float s = INV_S2;
    // forward level 1
    {
        float t[8];
#pragma unroll
        for (int j = 0; j < 4; j++) { t[j] = (a[2*j]+a[2*j+1])*s; t[j+4] = (a[2*j]-a[2*j+1])*s; }
#pragma unroll
        for (int j = 0; j < 8; j++) a[j] = t[j];
        int rr = r & 3;
        int s0 = (2*rr)*4 + b, s1 = s0 + 4;
        float sg = (r < 4) ? 1.f : -1.f;
#pragma unroll
        for (int j = 0; j < 8; j++) {
            float u0 = __shfl_sync(FM, a[j], s0);
            float u1 = __shfl_sync(FM, a[j], s1);
            a[j] = (u0 + sg*u1) * s;
        }
#pragma unroll
        for (int j = 0; j < 8; j++) if (r >= 4 || j >= 4) a[j] = softt(a[j]);
    }
    // forward level 2
    {
        if (r < 4) {
            float t0=(a[0]+a[1])*s, t1=(a[2]+a[3])*s, t2=(a[0]-a[1])*s, t3=(a[2]-a[3])*s;
            a[0]=t0; a[1]=t1; a[2]=t2; a[3]=t3;
        }
        int rr = r & 1;
        int s0 = (2*rr)*4 + b, s1 = s0 + 4;
        float sg = (r < 2) ? 1.f : -1.f;
#pragma unroll
        for (int j = 0; j < 4; j++) {
            float u0 = __shfl_sync(FM, a[j], s0);
            float u1 = __shfl_sync(FM, a[j], s1);
            if (r < 4) a[j] = (u0 + sg*u1) * s;
        }
#pragma unroll
        for (int j = 0; j < 4; j++) if (r < 4 && (r >= 2 || j >= 2)) a[j] = softt(a[j]);
    }
    // forward level 3
    {
        if (r < 2) {
            float t0=(a[0]+a[1])*s, t1=(a[0]-a[1])*s;
            a[0]=t0; a[1]=t1;
        }
        int s0 = b, s1 = 4 + b;
        float sg = (r == 0) ? 1.f : -1.f;
#pragma unroll
        for (int j = 0; j < 2; j++) {
            float u0 = __shfl_sync(FM, a[j], s0);
            float u1 = __shfl_sync(FM, a[j], s1);
            if (r < 2) a[j] = (u0 + sg*u1) * s;
        }
        if (r == 1) a[0] = softt(a[0]);
        if (r < 2)  a[1] = softt(a[1]);
    }
    // inverse level 3
    {
        int s0 = b, s1 = 4 + b;
        float sg = (r & 1) ? -1.f : 1.f;
#pragma unroll
        for (int j = 0; j < 2; j++) {
            float u0 = __shfl_sync(FM, a[j], s0);
            float u1 = __shfl_sync(FM, a[j], s1);
            if (r < 2) a[j] = (u0 + sg*u1) * s;
        }
        if (r < 2) {
            float t0=(a[0]+a[1])*s, t1=(a[0]-a[1])*s;
            a[0]=t0; a[1]=t1;
        }
    }
    // inverse level 2
    {
        int pj = (r >> 1) & 1;
        int s0 = pj*4 + b, s1 = (pj+2)*4 + b;
        float sg = (r & 1) ? -1.f : 1.f;
#pragma unroll
        for (int j = 0; j < 4; j++) {
            float u0 = __shfl_sync(FM, a[j], s0);
            float u1 = __shfl_sync(FM, a[j], s1);
            if (r < 4) a[j] = (u0 + sg*u1) * s;
        }
        if (r < 4) {
            float t0=(a[0]+a[2])*s, t1=(a[0]-a[2])*s, t2=(a[1]+a[3])*s, t3=(a[1]-a[3])*s;
            a[0]=t0; a[1]=t1; a[2]=t2; a[3]=t3;
        }
    }
    // inverse level 1
    {
        int pj = r >> 1;
        int s0 = pj*4 + b, s1 = (pj+4)*4 + b;
        float sg = (r & 1) ? -1.f : 1.f;
#pragma unroll
        for (int j = 0; j < 8; j++) {
            float u0 = __shfl_sync(FM, a[j], s0);
            float u1 = __shfl_sync(FM, a[j], s1);
            a[j] = (u0 + sg*u1) * s;
        }
        float t[8];
#pragma unroll
        for (int j = 0; j < 4; j++) { t[2*j] = (a[j]+a[j+4])*s; t[2*j+1] = (a[j]-a[j+4])*s; }
#pragma unroll
        for (int j = 0; j < 8; j++) a[j] = t[j];
    }
}

// ---------------- fused TV prox + wavelet + FISTA ----------------
#define TS 32
#define HL 6
#define TP 44
#define TPS 45
#define TVTH 512
__global__ void __launch_bounds__(TVTH) k_tvw(const float* __restrict__ xin,
                                              const float* __restrict__ xold,
                                              float* __restrict__ xnew,
                                              float* __restrict__ znew,
                                              float coef) {
    __shared__ float sx[TP*TPS], su[TP*TPS], spx[TP*TPS], spy[TP*TPS];
    __shared__ float sxo[TS][TS+1];
    int plane = blockIdx.x / 100;
    int t = blockIdx.x % 100;
    int gy0 = (t / 10) * TS - HL;
    int gx0 = (t % 10) * TS - HL;
    const float* X = xin + plane*NPLANE;
    for (int i = threadIdx.x; i < TP*TP; i += TVTH) {
        int r = i / TP, c = i - r*TP;
        int gy = gy0 + r, gx = gx0 + c;
        float v = 0.f;
        if (gy >= 0 && gy < HN && gx >= 0 && gx < HN) v = X[gy*HN + gx];
        sx[r*TPS+c] = v;
        spx[r*TPS+c] = 0.f;
        spy[r*TPS+c] = 0.f;
    }
    __syncthreads();
    for (int it = 0; it < 5; it++) {
        for (int i = threadIdx.x; i < TP*TP; i += TVTH) {
            int r = i / TP, c = i - r*TP;
            int gy = gy0 + r, gx = gx0 + c;
            float px_c = spx[r*TPS+c];
            float px_l = (c > 0) ? spx[r*TPS+c-1] : 0.f;
            float dx = (gx == 0) ? px_c : ((gx == HN-1) ? -px_l : px_c - px_l);
            float py_c = spy[r*TPS+c];
            float py_u = (r > 0) ? spy[(r-1)*TPS+c] : 0.f;
            float dy = (gy == 0) ? py_c : ((gy == HN-1) ? -py_u : py_c - py_u);
            su[r*TPS+c] = sx[r*TPS+c] - LAM_TV * (dx + dy);
        }
        __syncthreads();
        for (int i = threadIdx.x; i < TP*TP; i += TVTH) {
            int r = i / TP, c = i - r*TP;
            int gy = gy0 + r, gx = gx0 + c;
            float uc = su[r*TPS+c];
            float gxv = 0.f, gyv = 0.f;
            if (gx < HN-1 && c < TP-1) gxv = su[r*TPS+c+1] - uc;
            if (gy < HN-1 && r < TP-1) gyv = su[(r+1)*TPS+c] - uc;
            float pnx = spx[r*TPS+c] + 0.25f*gxv;
            float pny = spy[r*TPS+c] + 0.25f*gyv;
            float nrm = sqrtf(pnx*pnx + pny*pny + 1e-8f);
            float inv = (nrm > 1.f) ? 1.f/nrm : 1.f;
            if (gy < 0 || gy >= HN || gx < 0 || gx >= HN) { pnx = 0.f; pny = 0.f; inv = 1.f; }
            spx[r*TPS+c] = pnx*inv;
            spy[r*TPS+c] = pny*inv;
        }
        __syncthreads();
    }
    // TV output (interior 32x32) -> sxo
    for (int i = threadIdx.x; i < TS*TS; i += TVTH) {
        int rr = i / TS, cc = i - rr*TS;
        int r = rr + HL, c = cc + HL;
        int gy = gy0 + r, gx = gx0 + c;
        float px_c = spx[r*TPS+c];
        float px_l = spx[r*TPS+c-1];
        float dx = (gx == 0) ? px_c : ((gx == HN-1) ? -px_l : px_c - px_l);
        float py_c = spy[r*TPS+c];
        float py_u = spy[(r-1)*TPS+c];
        float dy = (gy == 0) ? py_c : ((gy == HN-1) ? -py_u : py_c - py_u);
        sxo[rr][cc] = sx[r*TPS+c] - LAM_TV * (dx + dy);
    }
    __syncthreads();
    // warp-parallel Haar: warps 0..3 each take an 8x32 strip (4 blocks of 8x8)
    int warp = threadIdx.x >> 5, lane = threadIdx.x & 31;
    if (warp < 4) {
        int r = lane >> 2, b = lane & 3;
        float a[8];
#pragma unroll
        for (int j = 0; j < 8; j++) a[j] = sxo[warp*8 + r][b*8 + j];
        warp_haar(a, r, b);
#pragma unroll
        for (int j = 0; j < 8; j++) sxo[warp*8 + r][b*8 + j] = a[j];
    }
    __syncthreads();
    // FISTA epilogue: coalesced
    const float* XO = xold + plane*NPLANE;
    float* XN = xnew + plane*NPLANE;
    float* ZN = znew + plane*NPLANE;
    int oy = gy0 + HL, ox = gx0 + HL;
    for (int i = threadIdx.x; i < TS*TS; i += TVTH) {
        int rr = i / TS, cc = i - rr*TS;
        int g = (oy + rr)*HN + ox + cc;
        float v = sxo[rr][cc];
        float xo = XO[g];
        XN[g] = v;
        ZN[g] = v + coef*(v - xo);
    }
}

// ---------------- host ----------------
extern "C" void kernel_launch(void* const* d_in, const int* in_sizes, int n_in,
                              void* d_out, int out_size) {
    (void)in_sizes; (void)n_in; (void)out_size;
    const float* y = (const float*)d_in[0];
    const float* mask = (const float*)d_in[1];
    float* out = (float*)d_out;

    float *Z, *X, *T1;
    float2 *T1c, *T2c;
    cudaGetSymbolAddress((void**)&Z,   g_Z);
    cudaGetSymbolAddress((void**)&X,   g_X);
    cudaGetSymbolAddress((void**)&T1,  g_T1);
    cudaGetSymbolAddress((void**)&T1c, g_T1c);
    cudaGetSymbolAddress((void**)&T2c, g_T2c);

    float coefs[15];
    {
        double t = 1.0;
        for (int k = 0; k < 15; k++) {
            double tn = (1.0 + sqrt(1.0 + 4.0*t*t)) / 2.0;
            coefs[k] = (float)((t - 1.0) / tn);
            t = tn;
        }
    }

    k_tw<<<1, 320>>>();
    k_prep<<<1600, 256>>>(y, mask);
    k_fft_p2c<<<FGRID, FTH>>>(y, T1c, -1.f, 1.0f);
    k_fft_c2p<<<FGRID, FTH>>>(T1c, X, Z, -1.f, 1.f/320.f);

    for (int it = 0; it < 15; it++) {
        k_fft_p2c<<<FGRID, FTH>>>(Z, T1c, 1.f, 1.f/320.f);
        k_fft_mid<<<FGRID, FTH>>>(T1c, T2c);
        k_fft_last<<<FGRID, FTH>>>(T2c, Z, T1);       // T1 = z_step
        float* xnew = (it == 14) ? out : X;
        k_tvw<<<3200, TVTH>>>(T1, X, xnew, Z, coefs[it]);
    }
}

// round 9
// speedup vs baseline: 1.2963x; 1.2963x over previous
#include <cuda_runtime.h>
#include <math.h>

#define HN 320
#define NPLANE (HN*HN)
#define NB 16
#define NTOT (NB*2*NPLANE)
#define LPC 4
#define FTH 128
#define GRPS (HN/LPC)
#define FGRID (NB*GRPS)          // 1280
#define LAM_TV 0.005f
#define LAM_W  0.005f
#define INV_S2 0.70710678118654752f

__device__ float  g_Z[NTOT];
__device__ float  g_X[NTOT];
__device__ float  g_T1[NTOT];            // planar z_step
__device__ float  g_T2[NTOT];            // planar x_tv
__device__ float2 g_T1c[NB*NPLANE];      // complex temp
__device__ float2 g_T2c[NB*NPLANE];      // complex temp
__device__ float2 g_ykc[NB*NPLANE];      // D*mask*y, transposed
__device__ float  g_mT[NB*NPLANE];       // mask, transposed
__device__ float2 g_tw[HN];

// ---------------- twiddles ----------------
__global__ void k_tw() {
    int k = threadIdx.x;
    if (k < HN) {
        double a = -2.0 * 3.14159265358979323846 * (double)k / (double)HN;
        g_tw[k] = make_float2((float)cos(a), (float)sin(a));
    }
}

// ---------------- prep ----------------
__global__ void __launch_bounds__(256) k_prep(const float* __restrict__ y,
                                              const float* __restrict__ mask) {
    __shared__ float sm[32][33], s0[32][33], s1[32][33];
    int b = blockIdx.x / 100, t = blockIdx.x % 100;
    int h0 = (t / 10) * 32, w0 = (t % 10) * 32;
    for (int i = threadIdx.x; i < 1024; i += 256) {
        int r = i >> 5, c = i & 31;
        sm[r][c] = mask[b*NPLANE + (h0+r)*HN + w0+c];
        s0[r][c] = y[(b*2+0)*NPLANE + (h0+r)*HN + w0+c];
        s1[r][c] = y[(b*2+1)*NPLANE + (h0+r)*HN + w0+c];
    }
    __syncthreads();
    for (int i = threadIdx.x; i < 1024; i += 256) {
        int ww = i >> 5, hh = i & 31;
        float sg = (((h0+hh) + (w0+ww)) & 1) ? -1.f : 1.f;
        float m = sm[hh][ww];
        int o = (w0+ww)*HN + h0+hh;
        g_mT[b*NPLANE + o] = m;
        g_ykc[b*NPLANE + o] = make_float2(sg*m*s0[hh][ww], sg*m*s1[hh][ww]);
    }
}

// ---------------- register/shuffle 320-pt FFT: 320 = 32(lanes) x 10(slots) ----------------
__device__ __forceinline__ float2 cmul(float2 a, float2 b) {
    return make_float2(a.x*b.x - a.y*b.y, a.x*b.y + a.y*b.x);
}

__device__ __forceinline__ void dft5(float2* v, float d) {
    const float c1 = 0.30901699437494742f, c2 = -0.80901699437494745f;
    const float s1 = 0.95105651629515353f, s2 = 0.58778525229247312f;
    float t1r=v[1].x+v[4].x, t1i=v[1].y+v[4].y;
    float t2r=v[2].x+v[3].x, t2i=v[2].y+v[3].y;
    float t3r=v[1].x-v[4].x, t3i=v[1].y-v[4].y;
    float t4r=v[2].x-v[3].x, t4i=v[2].y-v[3].y;
    float v0r=v[0].x, v0i=v[0].y;
    v[0] = make_float2(v0r+t1r+t2r, v0i+t1i+t2i);
    float a1r=v0r+c1*t1r+c2*t2r, a1i=v0i+c1*t1i+c2*t2i;
    float b1r=s1*t3r+s2*t4r,     b1i=s1*t3i+s2*t4i;
    float a2r=v0r+c2*t1r+c1*t2r, a2i=v0i+c2*t1i+c1*t2i;
    float b2r=s2*t3r-s1*t4r,     b2i=s2*t3i-s1*t4i;
    v[1] = make_float2(a1r + d*b1i, a1i - d*b1r);
    v[2] = make_float2(a2r + d*b2i, a2i - d*b2r);
    v[3] = make_float2(a2r - d*b2i, a2i + d*b2r);
    v[4] = make_float2(a1r - d*b1i, a1i + d*b1r);
}

__device__ __forceinline__ void dft10(float2* x, float d) {
    float2 E[5], O[5];
#pragma unroll
    for (int j = 0; j < 5; j++) { E[j] = x[2*j]; O[j] = x[2*j+1]; }
    dft5(E, d); dft5(O, d);
    const float C10[5] = {1.f, 0.80901699437494745f, 0.30901699437494742f,
                          -0.30901699437494742f, -0.80901699437494745f};
    const float S10[5] = {0.f, 0.58778525229247312f, 0.95105651629515353f,
                          0.95105651629515353f, 0.58778525229247312f};
#pragma unroll
    for (int k = 0; k < 5; k++) {
        float2 w = make_float2(C10[k], -d*S10[k]);
        float2 t = cmul(w, O[k]);
        x[k]   = make_float2(E[k].x + t.x, E[k].y + t.y);
        x[k+5] = make_float2(E[k].x - t.x, E[k].y - t.y);
    }
}

__device__ __forceinline__ void xfft32_dif(float2* x, const float2* stw, int lane, float d) {
#pragma unroll
    for (int s = 0; s < 5; s++) {
        const int m = 16 >> s;
        bool bot = (lane & m) != 0;
        int e = (lane & (m-1)) * ((16/m) * 10);
        float2 t = stw[e];
        float2 w = bot ? make_float2(t.x, d*t.y) : make_float2(1.f, 0.f);
        float sg = bot ? -1.f : 1.f;
#pragma unroll
        for (int j = 0; j < 10; j++) {
            float orr = __shfl_xor_sync(0xffffffffu, x[j].x, m);
            float oii = __shfl_xor_sync(0xffffffffu, x[j].y, m);
            float tr = orr + sg*x[j].x;
            float ti = oii + sg*x[j].y;
            x[j] = make_float2(tr*w.x - ti*w.y, tr*w.y + ti*w.x);
        }
    }
}

__device__ __forceinline__ void xfft32_dit_inv(float2* x, const float2* stw, int lane) {
#pragma unroll
    for (int s = 0; s < 5; s++) {
        const int m = 1 << s;
        bool bot = (lane & m) != 0;
        int e = (lane & (m-1)) * ((16/m) * 10);
        float2 t = stw[e];
        float2 w = make_float2(t.x, -t.y);
        float sg = bot ? -1.f : 1.f;
#pragma unroll
        for (int j = 0; j < 10; j++) {
            float orr = __shfl_xor_sync(0xffffffffu, x[j].x, m);
            float oii = __shfl_xor_sync(0xffffffffu, x[j].y, m);
            float pr = bot ? x[j].x : orr,  pi = bot ? x[j].y : oii;
            float qr = bot ? orr : x[j].x,  qi = bot ? oii : x[j].y;
            float wpr = pr*w.x - pi*w.y;
            float wpi = pr*w.y + pi*w.x;
            x[j] = make_float2(qr + sg*wpr, qi + sg*wpi);
        }
    }
}

__device__ __forceinline__ int fwd320(float2* x, const float2* stw, int lane, float d) {
    xfft32_dif(x, stw, lane, d);
    int k1 = __brev(lane) >> 27;
#pragma unroll
    for (int j = 1; j < 10; j++) {
        float2 t = stw[j*k1];
        x[j] = cmul(x[j], make_float2(t.x, d*t.y));
    }
    dft10(x, d);
    return k1;
}

__device__ __forceinline__ void inv320(float2* x, const float2* stw, int lane) {
    int k1 = __brev(lane) >> 27;
    dft10(x, -1.f);
#pragma unroll
    for (int j = 1; j < 10; j++) {
        float2 t = stw[j*k1];
        x[j] = cmul(x[j], make_float2(t.x, -t.y));
    }
    xfft32_dit_inv(x, stw, lane);
}

// ---------------- planar -> complex transposed (sign+scale at load) ----------------
__global__ void __launch_bounds__(FTH) k_fft_p2c(const float* __restrict__ src,
                                                 float2* __restrict__ dst,
                                                 float d, float scale) {
    __shared__ float2 stw[HN];
    __shared__ float2 SL[LPC][HN];
    int img = blockIdx.x / GRPS, r0 = (blockIdx.x % GRPS) * LPC;
    for (int i = threadIdx.x; i < HN; i += FTH) stw[i] = g_tw[i];
    __syncthreads();
    int warp = threadIdx.x >> 5, lane = threadIdx.x & 31;
    int r = r0 + warp;
    float2 x[10];
    float sgE = ((r) & 1) ? -scale : scale;
    float sgO = -sgE;
    const float2* sre = (const float2*)(src + (img*2+0)*NPLANE + r*HN + 10*lane);
    const float2* sim = (const float2*)(src + (img*2+1)*NPLANE + r*HN + 10*lane);
#pragma unroll
    for (int j = 0; j < 5; j++) {
        float2 vr = sre[j], vi = sim[j];
        x[2*j]   = make_float2(sgE*vr.x, sgE*vi.x);
        x[2*j+1] = make_float2(sgO*vr.y, sgO*vi.y);
    }
    int k1 = fwd320(x, stw, lane, d);
#pragma unroll
    for (int j = 0; j < 10; j++) SL[warp][32*j + k1] = x[j];
    __syncthreads();
    float2* D = dst + img*NPLANE;
    for (int i = threadIdx.x; i < LPC*HN; i += FTH) {
        int s = i & (LPC-1), k = i >> 2;
        D[k*HN + r0 + s] = SL[s][k];
    }
}

// ---------------- complex -> planar transposed, dual dst (init pass 2) ----------------
__global__ void __launch_bounds__(FTH) k_fft_c2p(const float2* __restrict__ src,
                                                 float* __restrict__ dstA,
                                                 float* __restrict__ dstB,
                                                 float d, float scale) {
    __shared__ float2 stw[HN];
    __shared__ float2 SL[LPC][HN];
    int img = blockIdx.x / GRPS, r0 = (blockIdx.x % GRPS) * LPC;
    for (int i = threadIdx.x; i < HN; i += FTH) stw[i] = g_tw[i];
    __syncthreads();
    int warp = threadIdx.x >> 5, lane = threadIdx.x & 31;
    int r = r0 + warp;
    float2 x[10];
    const float4* S4 = (const float4*)(src + img*NPLANE + r*HN + 10*lane);
#pragma unroll
    for (int j = 0; j < 5; j++) {
        float4 v = S4[j];
        x[2*j]   = make_float2(v.x, v.y);
        x[2*j+1] = make_float2(v.z, v.w);
    }
    int k1 = fwd320(x, stw, lane, d);
#pragma unroll
    for (int j = 0; j < 10; j++) SL[warp][32*j + k1] = x[j];
    __syncthreads();
    for (int i = threadIdx.x; i < LPC*HN; i += FTH) {
        int s = i & (LPC-1), k = i >> 2;
        float sg = ((k + r0 + s) & 1) ? -scale : scale;
        float2 v = SL[s][k];
        int o = k*HN + r0 + s;
        dstA[(img*2+0)*NPLANE + o] = sg*v.x;
        dstA[(img*2+1)*NPLANE + o] = sg*v.y;
        dstB[(img*2+0)*NPLANE + o] = sg*v.x;
        dstB[(img*2+1)*NPLANE + o] = sg*v.y;
    }
}

// ---------------- fwd col-FFT + mask + inv col-FFT ----------------
__global__ void __launch_bounds__(FTH) k_fft_mid(const float2* __restrict__ src,
                                                 float2* __restrict__ dst) {
    __shared__ float2 stw[HN];
    __shared__ float2 SL[LPC][HN];
    int img = blockIdx.x / GRPS, r0 = (blockIdx.x % GRPS) * LPC;
    for (int i = threadIdx.x; i < HN; i += FTH) stw[i] = g_tw[i];
    __syncthreads();
    int warp = threadIdx.x >> 5, lane = threadIdx.x & 31;
    int r = r0 + warp;
    float2 x[10];
    const float4* S4 = (const float4*)(src + img*NPLANE + r*HN + 10*lane);
#pragma unroll
    for (int j = 0; j < 5; j++) {
        float4 v = S4[j];
        x[2*j]   = make_float2(v.x, v.y);
        x[2*j+1] = make_float2(v.z, v.w);
    }
    int k1 = fwd320(x, stw, lane, 1.f);
    const float*  mrow = g_mT  + img*NPLANE + r*HN;
    const float2* ykr  = g_ykc + img*NPLANE + r*HN;
#pragma unroll
    for (int j = 0; j < 10; j++) {
        int kk = 32*j + k1;
        float m = mrow[kk];
        float2 yk = ykr[kk];
        x[j] = make_float2(x[j].x*m - yk.x, x[j].y*m - yk.y);
    }
    inv320(x, stw, lane);
#pragma unroll
    for (int j = 0; j < 10; j++) SL[warp][10*lane + j] = x[j];
    __syncthreads();
    float2* D = dst + img*NPLANE;
    for (int i = threadIdx.x; i < LPC*HN; i += FTH) {
        int s = i & (LPC-1), k = i >> 2;
        D[k*HN + r0 + s] = SL[s][k];
    }
}

// ---------------- inv row-FFT + fused z_step = z - g ----------------
__global__ void __launch_bounds__(FTH) k_fft_last(const float2* __restrict__ src,
                                                  const float* __restrict__ zin,
                                                  float* __restrict__ zs) {
    __shared__ float2 stw[HN];
    __shared__ float2 SL[LPC][HN];
    int img = blockIdx.x / GRPS, r0 = (blockIdx.x % GRPS) * LPC;
    for (int i = threadIdx.x; i < HN; i += FTH) stw[i] = g_tw[i];
    __syncthreads();
    int warp = threadIdx.x >> 5, lane = threadIdx.x & 31;
    int r = r0 + warp;
    float2 x[10];
    const float4* S4 = (const float4*)(src + img*NPLANE + r*HN + 10*lane);
#pragma unroll
    for (int j = 0; j < 5; j++) {
        float4 v = S4[j];
        x[2*j]   = make_float2(v.x, v.y);
        x[2*j+1] = make_float2(v.z, v.w);
    }
    int k1 = fwd320(x, stw, lane, -1.f);
#pragma unroll
    for (int j = 0; j < 10; j++) SL[warp][32*j + k1] = x[j];
    __syncthreads();
    const float sc = 1.f/320.f;
    for (int i = threadIdx.x; i < LPC*HN; i += FTH) {
        int s = i / HN, w = i - s*HN;
        float sg = (((r0+s) + w) & 1) ? -sc : sc;
        float2 v = SL[s][w];
        int oR = (img*2+0)*NPLANE + (r0+s)*HN + w;
        int oI = (img*2+1)*NPLANE + (r0+s)*HN + w;
        zs[oR] = zin[oR] - sg*v.x;
        zs[oI] = zin[oI] - sg*v.y;
    }
}

// ---------------- TV prox: 64x64 tile, 5 fused Chambolle iterations ----------------
#define TS 64
#define HL 6
#define TP 76
#define TPS 77
#define TVTH 1024
#define TVSMEM (4*TP*TPS*4)
__global__ void __launch_bounds__(TVTH) k_tv(const float* __restrict__ xin,
                                             float* __restrict__ xout) {
    extern __shared__ float smem[];
    float* sx  = smem;
    float* su  = smem + TP*TPS;
    float* spx = smem + 2*TP*TPS;
    float* spy = smem + 3*TP*TPS;
    int plane = blockIdx.x / 25;
    int t = blockIdx.x % 25;
    int gy0 = (t / 5) * TS - HL;
    int gx0 = (t % 5) * TS - HL;
    const float* X = xin + plane*NPLANE;
    for (int i = threadIdx.x; i < TP*TP; i += TVTH) {
        int r = i / TP, c = i - r*TP;
        int gy = gy0 + r, gx = gx0 + c;
        float v = 0.f;
        if (gy >= 0 && gy < HN && gx >= 0 && gx < HN) v = X[gy*HN + gx];
        sx[r*TPS+c] = v;
        spx[r*TPS+c] = 0.f;
        spy[r*TPS+c] = 0.f;
    }
    __syncthreads();
    for (int it = 0; it < 5; it++) {
        for (int i = threadIdx.x; i < TP*TP; i += TVTH) {
            int r = i / TP, c = i - r*TP;
            int gy = gy0 + r, gx = gx0 + c;
            float px_c = spx[r*TPS+c];
            float px_l = (c > 0) ? spx[r*TPS+c-1] : 0.f;
            float dx = (gx == 0) ? px_c : ((gx == HN-1) ? -px_l : px_c - px_l);
            float py_c = spy[r*TPS+c];
            float py_u = (r > 0) ? spy[(r-1)*TPS+c] : 0.f;
            float dy = (gy == 0) ? py_c : ((gy == HN-1) ? -py_u : py_c - py_u);
            su[r*TPS+c] = sx[r*TPS+c] - LAM_TV * (dx + dy);
        }
        __syncthreads();
        for (int i = threadIdx.x; i < TP*TP; i += TVTH) {
            int r = i / TP, c = i - r*TP;
            int gy = gy0 + r, gx = gx0 + c;
            float uc = su[r*TPS+c];
            float gxv = 0.f, gyv = 0.f;
            if (gx < HN-1 && c < TP-1) gxv = su[r*TPS+c+1] - uc;
            if (gy < HN-1 && r < TP-1) gyv = su[(r+1)*TPS+c] - uc;
            float pnx = spx[r*TPS+c] + 0.25f*gxv;
            float pny = spy[r*TPS+c] + 0.25f*gyv;
            float nrm = sqrtf(pnx*pnx + pny*pny + 1e-8f);
            float inv = (nrm > 1.f) ? 1.f/nrm : 1.f;
            if (gy < 0 || gy >= HN || gx < 0 || gx >= HN) { pnx = 0.f; pny = 0.f; inv = 1.f; }
            spx[r*TPS+c] = pnx*inv;
            spy[r*TPS+c] = pny*inv;
        }
        __syncthreads();
    }
    float* O = xout + plane*NPLANE;
    for (int i = threadIdx.x; i < TS*TS; i += TVTH) {
        int rr = i / TS, cc = i - rr*TS;
        int r = rr + HL, c = cc + HL;
        int gy = gy0 + r, gx = gx0 + c;
        float px_c = spx[r*TPS+c];
        float px_l = spx[r*TPS+c-1];
        float dx = (gx == 0) ? px_c : ((gx == HN-1) ? -px_l : px_c - px_l);
        float py_c = spy[r*TPS+c];
        float py_u = spy[(r-1)*TPS+c];
        float dy = (gy == 0) ? py_c : ((gy == HN-1) ? -py_u : py_c - py_u);
        O[gy*HN + gx] = sx[r*TPS+c] - LAM_TV * (dx + dy);
    }
}

// ---------------- warp-parallel 3-level Haar + soft-threshold + FISTA ----------------
// One warp = 8x32 strip = four 8x8 blocks. lane = row*4 + blk.
__device__ __forceinline__ float softt(float v) {
    float m = fabsf(v) - LAM_W;
    return (m > 0.f) ? copysignf(m, v) : 0.f;
}

__global__ void __launch_bounds__(256) k_wav(const float* __restrict__ xtv,
                                             const float* __restrict__ xold,
                                             float* __restrict__ xnew,
                                             float* __restrict__ znew,
                                             float coef) {
    const unsigned FM = 0xffffffffu;
    const float s = INV_S2;
    int gw = (blockIdx.x * 256 + threadIdx.x) >> 5;   // 0..12799
    int lane = threadIdx.x & 31;
    int plane = gw / 400;
    int rem = gw - plane*400;
    int rowblk = rem / 10, colgrp = rem - rowblk*10;
    int r = lane >> 2, b = lane & 3;
    int base = plane*NPLANE + (rowblk*8 + r)*HN + colgrp*32 + b*8;

    float a[8];
    {
        float4 v0 = *(const float4*)(xtv + base);
        float4 v1 = *(const float4*)(xtv + base + 4);
        a[0]=v0.x; a[1]=v0.y; a[2]=v0.z; a[3]=v0.w;
        a[4]=v1.x; a[5]=v1.y; a[6]=v1.z; a[7]=v1.w;
    }

    // ===== forward level 1 =====
    {
        float t[8];
#pragma unroll
        for (int j = 0; j < 4; j++) { t[j] = (a[2*j]+a[2*j+1])*s; t[j+4] = (a[2*j]-a[2*j+1])*s; }
#pragma unroll
        for (int j = 0; j < 8; j++) a[j] = t[j];
        int rr = r & 3;
        int s0 = (2*rr)*4 + b, s1 = s0 + 4;
        float sg = (r < 4) ? 1.f : -1.f;
#pragma unroll
        for (int j = 0; j < 8; j++) {
            float u0 = __shfl_sync(FM, a[j], s0);
            float u1 = __shfl_sync(FM, a[j], s1);
            a[j] = (u0 + sg*u1) * s;
        }
#pragma unroll
        for (int j = 0; j < 8; j++) if (r >= 4 || j >= 4) a[j] = softt(a[j]);
    }
    // ===== forward level 2 =====
    {
        if (r < 4) {
            float t0=(a[0]+a[1])*s, t1=(a[2]+a[3])*s, t2=(a[0]-a[1])*s, t3=(a[2]-a[3])*s;
            a[0]=t0; a[1]=t1; a[2]=t2; a[3]=t3;
        }
        int rr = r & 1;
        int s0 = (2*rr)*4 + b, s1 = s0 + 4;
        float sg = (r < 2) ? 1.f : -1.f;
#pragma unroll
        for (int j = 0; j < 4; j++) {
            float u0 = __shfl_sync(FM, a[j], s0);
            float u1 = __shfl_sync(FM, a[j], s1);
            if (r < 4) a[j] = (u0 + sg*u1) * s;
        }
#pragma unroll
        for (int j = 0; j < 4; j++) if (r < 4 && (r >= 2 || j >= 2)) a[j] = softt(a[j]);
    }
    // ===== forward level 3 =====
    {
        if (r < 2) {
            float t0=(a[0]+a[1])*s, t1=(a[0]-a[1])*s;
            a[0]=t0; a[1]=t1;
        }
        int s0 = b, s1 = 4 + b;
        float sg = (r == 0) ? 1.f : -1.f;
#pragma unroll
        for (int j = 0; j < 2; j++) {
            float u0 = __shfl_sync(FM, a[j], s0);
            float u1 = __shfl_sync(FM, a[j], s1);
            if (r < 2) a[j] = (u0 + sg*u1) * s;
        }
        if (r == 1) a[0] = softt(a[0]);
        if (r < 2)  a[1] = softt(a[1]);
    }
    // ===== inverse level 3 =====
    {
        int s0 = b, s1 = 4 + b;
        float sg = (r & 1) ? -1.f : 1.f;
#pragma unroll
        for (int j = 0; j < 2; j++) {
            float u0 = __shfl_sync(FM, a[j], s0);
            float u1 = __shfl_sync(FM, a[j], s1);
            if (r < 2) a[j] = (u0 + sg*u1) * s;
        }
        if (r < 2) {
            float t0=(a[0]+a[1])*s, t1=(a[0]-a[1])*s;
            a[0]=t0; a[1]=t1;
        }
    }
    // ===== inverse level 2 =====
    {
        int pj = (r >> 1) & 1;
        int s0 = pj*4 + b, s1 = (pj+2)*4 + b;
        float sg = (r & 1) ? -1.f : 1.f;
#pragma unroll
        for (int j = 0; j < 4; j++) {
            float u0 = __shfl_sync(FM, a[j], s0);
            float u1 = __shfl_sync(FM, a[j], s1);
            if (r < 4) a[j] = (u0 + sg*u1) * s;
        }
        if (r < 4) {
            float t0=(a[0]+a[2])*s, t1=(a[0]-a[2])*s, t2=(a[1]+a[3])*s, t3=(a[1]-a[3])*s;
            a[0]=t0; a[1]=t1; a[2]=t2; a[3]=t3;
        }
    }
    // ===== inverse level 1 =====
    {
        int pj = r >> 1;
        int s0 = pj*4 + b, s1 = (pj+4)*4 + b;
        float sg = (r & 1) ? -1.f : 1.f;
#pragma unroll
        for (int j = 0; j < 8; j++) {
            float u0 = __shfl_sync(FM, a[j], s0);
            float u1 = __shfl_sync(FM, a[j], s1);
            a[j] = (u0 + sg*u1) * s;
        }
        float t[8];
#pragma unroll
        for (int j = 0; j < 4; j++) { t[2*j] = (a[j]+a[j+4])*s; t[2*j+1] = (a[j]-a[j+4])*s; }
#pragma unroll
        for (int j = 0; j < 8; j++) a[j] = t[j];
    }
    // ===== FISTA epilogue =====
    {
        float4 xo0 = *(const float4*)(xold + base);
        float4 xo1 = *(const float4*)(xold + base + 4);
        float xov[8] = {xo0.x,xo0.y,xo0.z,xo0.w,xo1.x,xo1.y,xo1.z,xo1.w};
        float xn[8], zn[8];
#pragma unroll
        for (int j = 0; j < 8; j++) {
            float v = a[j];
            xn[j] = v;
            zn[j] = v + coef*(v - xov[j]);
        }
        *(float4*)(xnew + base)     = make_float4(xn[0],xn[1],xn[2],xn[3]);
        *(float4*)(xnew + base + 4) = make_float4(xn[4],xn[5],xn[6],xn[7]);
        *(float4*)(znew + base)     = make_float4(zn[0],zn[1],zn[2],zn[3]);
        *(float4*)(znew + base + 4) = make_float4(zn[4],zn[5],zn[6],zn[7]);
    }
}

// ---------------- host ----------------
extern "C" void kernel_launch(void* const* d_in, const int* in_sizes, int n_in,
                              void* d_out, int out_size) {
    (void)in_sizes; (void)n_in; (void)out_size;
    const float* y = (const float*)d_in[0];
    const float* mask = (const float*)d_in[1];
    float* out = (float*)d_out;

    float *Z, *X, *T1, *T2;
    float2 *T1c, *T2c;
    cudaGetSymbolAddress((void**)&Z,   g_Z);
    cudaGetSymbolAddress((void**)&X,   g_X);
    cudaGetSymbolAddress((void**)&T1,  g_T1);
    cudaGetSymbolAddress((void**)&T2,  g_T2);
    cudaGetSymbolAddress((void**)&T1c, g_T1c);
    cudaGetSymbolAddress((void**)&T2c, g_T2c);

    cudaFuncSetAttribute(k_tv, cudaFuncAttributeMaxDynamicSharedMemorySize, TVSMEM);

    float coefs[15];
    {
        double t = 1.0;
        for (int k = 0; k < 15; k++) {
            double tn = (1.0 + sqrt(1.0 + 4.0*t*t)) / 2.0;
            coefs[k] = (float)((t - 1.0) / tn);
            t = tn;
        }
    }

    k_tw<<<1, 320>>>();
    k_prep<<<1600, 256>>>(y, mask);
    k_fft_p2c<<<FGRID, FTH>>>(y, T1c, -1.f, 1.0f);
    k_fft_c2p<<<FGRID, FTH>>>(T1c, X, Z, -1.f, 1.f/320.f);

    for (int it = 0; it < 15; it++) {
        k_fft_p2c<<<FGRID, FTH>>>(Z, T1c, 1.f, 1.f/320.f);
        k_fft_mid<<<FGRID, FTH>>>(T1c, T2c);
        k_fft_last<<<FGRID, FTH>>>(T2c, Z, T1);       // T1 = z_step
        k_tv<<<800, TVTH, TVSMEM>>>(T1, T2);          // T2 = x_tv
        float* xnew = (it == 14) ? out : X;
        k_wav<<<1600, 256>>>(T2, X, xnew, Z, coefs[it]);
    }
}

// round 10
// speedup vs baseline: 1.5043x; 1.1604x over previous
#include <cuda_runtime.h>
#include <math.h>

#define HN 320
#define NPLANE (HN*HN)
#define NB 16
#define NTOT (NB*2*NPLANE)
#define LPC 4
#define FTH 128
#define GRPS (HN/LPC)
#define FGRID (NB*GRPS)          // 1280 (full batch)
#define NCH 4                    // chains
#define IPC (NB/NCH)             // images per chain = 4
#define FG2 (IPC*GRPS)           // 320 blocks per chain FFT
#define LAM_TV 0.005f
#define LAM_W  0.005f
#define INV_S2 0.70710678118654752f

__device__ float  g_Z[NTOT];
__device__ float  g_X[NTOT];
__device__ float  g_T1[NTOT];            // planar z_step
__device__ float  g_T2[NTOT];            // planar x_tv
__device__ float2 g_T1c[NB*NPLANE];      // complex temp
__device__ float2 g_T2c[NB*NPLANE];      // complex temp
__device__ float2 g_ykc[NB*NPLANE];      // D*mask*y, transposed
__device__ float  g_mT[NB*NPLANE];       // mask, transposed
__device__ float2 g_tw[HN];

// ---------------- twiddles ----------------
__global__ void k_tw() {
    int k = threadIdx.x;
    if (k < HN) {
        double a = -2.0 * 3.14159265358979323846 * (double)k / (double)HN;
        g_tw[k] = make_float2((float)cos(a), (float)sin(a));
    }
}

// ---------------- prep ----------------
__global__ void __launch_bounds__(256) k_prep(const float* __restrict__ y,
                                              const float* __restrict__ mask) {
    __shared__ float sm[32][33], s0[32][33], s1[32][33];
    int b = blockIdx.x / 100, t = blockIdx.x % 100;
    int h0 = (t / 10) * 32, w0 = (t % 10) * 32;
    for (int i = threadIdx.x; i < 1024; i += 256) {
        int r = i >> 5, c = i & 31;
        sm[r][c] = mask[b*NPLANE + (h0+r)*HN + w0+c];
        s0[r][c] = y[(b*2+0)*NPLANE + (h0+r)*HN + w0+c];
        s1[r][c] = y[(b*2+1)*NPLANE + (h0+r)*HN + w0+c];
    }
    __syncthreads();
    for (int i = threadIdx.x; i < 1024; i += 256) {
        int ww = i >> 5, hh = i & 31;
        float sg = (((h0+hh) + (w0+ww)) & 1) ? -1.f : 1.f;
        float m = sm[hh][ww];
        int o = (w0+ww)*HN + h0+hh;
        g_mT[b*NPLANE + o] = m;
        g_ykc[b*NPLANE + o] = make_float2(sg*m*s0[hh][ww], sg*m*s1[hh][ww]);
    }
}

// ---------------- register/shuffle 320-pt FFT: 320 = 32(lanes) x 10(slots) ----------------
__device__ __forceinline__ float2 cmul(float2 a, float2 b) {
    return make_float2(a.x*b.x - a.y*b.y, a.x*b.y + a.y*b.x);
}

__device__ __forceinline__ void dft5(float2* v, float d) {
    const float c1 = 0.30901699437494742f, c2 = -0.80901699437494745f;
    const float s1 = 0.95105651629515353f, s2 = 0.58778525229247312f;
    float t1r=v[1].x+v[4].x, t1i=v[1].y+v[4].y;
    float t2r=v[2].x+v[3].x, t2i=v[2].y+v[3].y;
    float t3r=v[1].x-v[4].x, t3i=v[1].y-v[4].y;
    float t4r=v[2].x-v[3].x, t4i=v[2].y-v[3].y;
    float v0r=v[0].x, v0i=v[0].y;
    v[0] = make_float2(v0r+t1r+t2r, v0i+t1i+t2i);
    float a1r=v0r+c1*t1r+c2*t2r, a1i=v0i+c1*t1i+c2*t2i;
    float b1r=s1*t3r+s2*t4r,     b1i=s1*t3i+s2*t4i;
    float a2r=v0r+c2*t1r+c1*t2r, a2i=v0i+c2*t1i+c1*t2i;
    float b2r=s2*t3r-s1*t4r,     b2i=s2*t3i-s1*t4i;
    v[1] = make_float2(a1r + d*b1i, a1i - d*b1r);
    v[2] = make_float2(a2r + d*b2i, a2i - d*b2r);
    v[3] = make_float2(a2r - d*b2i, a2i + d*b2r);
    v[4] = make_float2(a1r - d*b1i, a1i + d*b1r);
}

__device__ __forceinline__ void dft10(float2* x, float d) {
    float2 E[5], O[5];
#pragma unroll
    for (int j = 0; j < 5; j++) { E[j] = x[2*j]; O[j] = x[2*j+1]; }
    dft5(E, d); dft5(O, d);
    const float C10[5] = {1.f, 0.80901699437494745f, 0.30901699437494742f,
                          -0.30901699437494742f, -0.80901699437494745f};
    const float S10[5] = {0.f, 0.58778525229247312f, 0.95105651629515353f,
                          0.95105651629515353f, 0.58778525229247312f};
#pragma unroll
    for (int k = 0; k < 5; k++) {
        float2 w = make_float2(C10[k], -d*S10[k]);
        float2 t = cmul(w, O[k]);
        x[k]   = make_float2(E[k].x + t.x, E[k].y + t.y);
        x[k+5] = make_float2(E[k].x - t.x, E[k].y - t.y);
    }
}

__device__ __forceinline__ void xfft32_dif(float2* x, const float2* stw, int lane, float d) {
#pragma unroll
    for (int s = 0; s < 5; s++) {
        const int m = 16 >> s;
        bool bot = (lane & m) != 0;
        int e = (lane & (m-1)) * ((16/m) * 10);
        float2 t = stw[e];
        float2 w = bot ? make_float2(t.x, d*t.y) : make_float2(1.f, 0.f);
        float sg = bot ? -1.f : 1.f;
#pragma unroll
        for (int j = 0; j < 10; j++) {
            float orr = __shfl_xor_sync(0xffffffffu, x[j].x, m);
            float oii = __shfl_xor_sync(0xffffffffu, x[j].y, m);
            float tr = orr + sg*x[j].x;
            float ti = oii + sg*x[j].y;
            x[j] = make_float2(tr*w.x - ti*w.y, tr*w.y + ti*w.x);
        }
    }
}

__device__ __forceinline__ void xfft32_dit_inv(float2* x, const float2* stw, int lane) {
#pragma unroll
    for (int s = 0; s < 5; s++) {
        const int m = 1 << s;
        bool bot = (lane & m) != 0;
        int e = (lane & (m-1)) * ((16/m) * 10);
        float2 t = stw[e];
        float2 w = make_float2(t.x, -t.y);
        float sg = bot ? -1.f : 1.f;
#pragma unroll
        for (int j = 0; j < 10; j++) {
            float orr = __shfl_xor_sync(0xffffffffu, x[j].x, m);
            float oii = __shfl_xor_sync(0xffffffffu, x[j].y, m);
            float pr = bot ? x[j].x : orr,  pi = bot ? x[j].y : oii;
            float qr = bot ? orr : x[j].x,  qi = bot ? oii : x[j].y;
            float wpr = pr*w.x - pi*w.y;
            float wpi = pr*w.y + pi*w.x;
            x[j] = make_float2(qr + sg*wpr, qi + sg*wpi);
        }
    }
}

__device__ __forceinline__ int fwd320(float2* x, const float2* stw, int lane, float d) {
    xfft32_dif(x, stw, lane, d);
    int k1 = __brev(lane) >> 27;
#pragma unroll
    for (int j = 1; j < 10; j++) {
        float2 t = stw[j*k1];
        x[j] = cmul(x[j], make_float2(t.x, d*t.y));
    }
    dft10(x, d);
    return k1;
}

__device__ __forceinline__ void inv320(float2* x, const float2* stw, int lane) {
    int k1 = __brev(lane) >> 27;
    dft10(x, -1.f);
#pragma unroll
    for (int j = 1; j < 10; j++) {
        float2 t = stw[j*k1];
        x[j] = cmul(x[j], make_float2(t.x, -t.y));
    }
    xfft32_dit_inv(x, stw, lane);
}

// ---------------- planar -> complex transposed (sign+scale at load) ----------------
__global__ void __launch_bounds__(FTH) k_fft_p2c(const float* __restrict__ src,
                                                 float2* __restrict__ dst,
                                                 float d, float scale, int img0) {
    __shared__ float2 stw[HN];
    __shared__ float2 SL[LPC][HN];
    int img = img0 + blockIdx.x / GRPS, r0 = (blockIdx.x % GRPS) * LPC;
    for (int i = threadIdx.x; i < HN; i += FTH) stw[i] = g_tw[i];
    __syncthreads();
    int warp = threadIdx.x >> 5, lane = threadIdx.x & 31;
    int r = r0 + warp;
    float2 x[10];
    float sgE = ((r) & 1) ? -scale : scale;
    float sgO = -sgE;
    const float2* sre = (const float2*)(src + (img*2+0)*NPLANE + r*HN + 10*lane);
    const float2* sim = (const float2*)(src + (img*2+1)*NPLANE + r*HN + 10*lane);
#pragma unroll
    for (int j = 0; j < 5; j++) {
        float2 vr = sre[j], vi = sim[j];
        x[2*j]   = make_float2(sgE*vr.x, sgE*vi.x);
        x[2*j+1] = make_float2(sgO*vr.y, sgO*vi.y);
    }
    int k1 = fwd320(x, stw, lane, d);
#pragma unroll
    for (int j = 0; j < 10; j++) SL[warp][32*j + k1] = x[j];
    __syncthreads();
    float2* D = dst + img*NPLANE;
    for (int i = threadIdx.x; i < LPC*HN; i += FTH) {
        int s = i & (LPC-1), k = i >> 2;
        D[k*HN + r0 + s] = SL[s][k];
    }
}

// ---------------- complex -> planar transposed, dual dst (init pass 2) ----------------
__global__ void __launch_bounds__(FTH) k_fft_c2p(const float2* __restrict__ src,
                                                 float* __restrict__ dstA,
                                                 float* __restrict__ dstB,
                                                 float d, float scale, int img0) {
    __shared__ float2 stw[HN];
    __shared__ float2 SL[LPC][HN];
    int img = img0 + blockIdx.x / GRPS, r0 = (blockIdx.x % GRPS) * LPC;
    for (int i = threadIdx.x; i < HN; i += FTH) stw[i] = g_tw[i];
    __syncthreads();
    int warp = threadIdx.x >> 5, lane = threadIdx.x & 31;
    int r = r0 + warp;
    float2 x[10];
    const float4* S4 = (const float4*)(src + img*NPLANE + r*HN + 10*lane);
#pragma unroll
    for (int j = 0; j < 5; j++) {
        float4 v = S4[j];
        x[2*j]   = make_float2(v.x, v.y);
        x[2*j+1] = make_float2(v.z, v.w);
    }
    int k1 = fwd320(x, stw, lane, d);
#pragma unroll
    for (int j = 0; j < 10; j++) SL[warp][32*j + k1] = x[j];
    __syncthreads();
    for (int i = threadIdx.x; i < LPC*HN; i += FTH) {
        int s = i & (LPC-1), k = i >> 2;
        float sg = ((k + r0 + s) & 1) ? -scale : scale;
        float2 v = SL[s][k];
        int o = k*HN + r0 + s;
        dstA[(img*2+0)*NPLANE + o] = sg*v.x;
        dstA[(img*2+1)*NPLANE + o] = sg*v.y;
        dstB[(img*2+0)*NPLANE + o] = sg*v.x;
        dstB[(img*2+1)*NPLANE + o] = sg*v.y;
    }
}

// ---------------- fwd col-FFT + mask + inv col-FFT ----------------
__global__ void __launch_bounds__(FTH) k_fft_mid(const float2* __restrict__ src,
                                                 float2* __restrict__ dst, int img0) {
    __shared__ float2 stw[HN];
    __shared__ float2 SL[LPC][HN];
    int img = img0 + blockIdx.x / GRPS, r0 = (blockIdx.x % GRPS) * LPC;
    for (int i = threadIdx.x; i < HN; i += FTH) stw[i] = g_tw[i];
    __syncthreads();
    int warp = threadIdx.x >> 5, lane = threadIdx.x & 31;
    int r = r0 + warp;
    float2 x[10];
    const float4* S4 = (const float4*)(src + img*NPLANE + r*HN + 10*lane);
#pragma unroll
    for (int j = 0; j < 5; j++) {
        float4 v = S4[j];
        x[2*j]   = make_float2(v.x, v.y);
        x[2*j+1] = make_float2(v.z, v.w);
    }
    int k1 = fwd320(x, stw, lane, 1.f);
    const float*  mrow = g_mT  + img*NPLANE + r*HN;
    const float2* ykr  = g_ykc + img*NPLANE + r*HN;
#pragma unroll
    for (int j = 0; j < 10; j++) {
        int kk = 32*j + k1;
        float m = mrow[kk];
        float2 yk = ykr[kk];
        x[j] = make_float2(x[j].x*m - yk.x, x[j].y*m - yk.y);
    }
    inv320(x, stw, lane);
#pragma unroll
    for (int j = 0; j < 10; j++) SL[warp][10*lane + j] = x[j];
    __syncthreads();
    float2* D = dst + img*NPLANE;
    for (int i = threadIdx.x; i < LPC*HN; i += FTH) {
        int s = i & (LPC-1), k = i >> 2;
        D[k*HN + r0 + s] = SL[s][k];
    }
}

// ---------------- inv row-FFT + fused z_step = z - g ----------------
__global__ void __launch_bounds__(FTH) k_fft_last(const float2* __restrict__ src,
                                                  const float* __restrict__ zin,
                                                  float* __restrict__ zs, int img0) {
    __shared__ float2 stw[HN];
    __shared__ float2 SL[LPC][HN];
    int img = img0 + blockIdx.x / GRPS, r0 = (blockIdx.x % GRPS) * LPC;
    for (int i = threadIdx.x; i < HN; i += FTH) stw[i] = g_tw[i];
    __syncthreads();
    int warp = threadIdx.x >> 5, lane = threadIdx.x & 31;
    int r = r0 + warp;
    float2 x[10];
    const float4* S4 = (const float4*)(src + img*NPLANE + r*HN + 10*lane);
#pragma unroll
    for (int j = 0; j < 5; j++) {
        float4 v = S4[j];
        x[2*j]   = make_float2(v.x, v.y);
        x[2*j+1] = make_float2(v.z, v.w);
    }
    int k1 = fwd320(x, stw, lane, -1.f);
#pragma unroll
    for (int j = 0; j < 10; j++) SL[warp][32*j + k1] = x[j];
    __syncthreads();
    const float sc = 1.f/320.f;
    for (int i = threadIdx.x; i < LPC*HN; i += FTH) {
        int s = i / HN, w = i - s*HN;
        float sg = (((r0+s) + w) & 1) ? -sc : sc;
        float2 v = SL[s][w];
        int oR = (img*2+0)*NPLANE + (r0+s)*HN + w;
        int oI = (img*2+1)*NPLANE + (r0+s)*HN + w;
        zs[oR] = zin[oR] - sg*v.x;
        zs[oI] = zin[oI] - sg*v.y;
    }
}

// ---------------- TV prox: 64x64 tile, 5 fused Chambolle iterations ----------------
#define TS 64
#define HL 6
#define TP 76
#define TPS 77
#define TVTH 1024
#define TVSMEM (4*TP*TPS*4)
__global__ void __launch_bounds__(TVTH) k_tv(const float* __restrict__ xin,
                                             float* __restrict__ xout, int plane0) {
    extern __shared__ float smem[];
    float* sx  = smem;
    float* su  = smem + TP*TPS;
    float* spx = smem + 2*TP*TPS;
    float* spy = smem + 3*TP*TPS;
    int plane = plane0 + blockIdx.x / 25;
    int t = blockIdx.x % 25;
    int gy0 = (t / 5) * TS - HL;
    int gx0 = (t % 5) * TS - HL;
    const float* X = xin + plane*NPLANE;
    for (int i = threadIdx.x; i < TP*TP; i += TVTH) {
        int r = i / TP, c = i - r*TP;
        int gy = gy0 + r, gx = gx0 + c;
        float v = 0.f;
        if (gy >= 0 && gy < HN && gx >= 0 && gx < HN) v = X[gy*HN + gx];
        sx[r*TPS+c] = v;
        spx[r*TPS+c] = 0.f;
        spy[r*TPS+c] = 0.f;
    }
    __syncthreads();
    for (int it = 0; it < 5; it++) {
        for (int i = threadIdx.x; i < TP*TP; i += TVTH) {
            int r = i / TP, c = i - r*TP;
            int gy = gy0 + r, gx = gx0 + c;
            float px_c = spx[r*TPS+c];
            float px_l = (c > 0) ? spx[r*TPS+c-1] : 0.f;
            float dx = (gx == 0) ? px_c : ((gx == HN-1) ? -px_l : px_c - px_l);
            float py_c = spy[r*TPS+c];
            float py_u = (r > 0) ? spy[(r-1)*TPS+c] : 0.f;
            float dy = (gy == 0) ? py_c : ((gy == HN-1) ? -py_u : py_c - py_u);
            su[r*TPS+c] = sx[r*TPS+c] - LAM_TV * (dx + dy);
        }
        __syncthreads();
        for (int i = threadIdx.x; i < TP*TP; i += TVTH) {
            int r = i / TP, c = i - r*TP;
            int gy = gy0 + r, gx = gx0 + c;
            float uc = su[r*TPS+c];
            float gxv = 0.f, gyv = 0.f;
            if (gx < HN-1 && c < TP-1) gxv = su[r*TPS+c+1] - uc;
            if (gy < HN-1 && r < TP-1) gyv = su[(r+1)*TPS+c] - uc;
            float pnx = spx[r*TPS+c] + 0.25f*gxv;
            float pny = spy[r*TPS+c] + 0.25f*gyv;
            float nrm = sqrtf(pnx*pnx + pny*pny + 1e-8f);
            float inv = (nrm > 1.f) ? 1.f/nrm : 1.f;
            if (gy < 0 || gy >= HN || gx < 0 || gx >= HN) { pnx = 0.f; pny = 0.f; inv = 1.f; }
            spx[r*TPS+c] = pnx*inv;
            spy[r*TPS+c] = pny*inv;
        }
        __syncthreads();
    }
    float* O = xout + plane*NPLANE;
    for (int i = threadIdx.x; i < TS*TS; i += TVTH) {
        int rr = i / TS, cc = i - rr*TS;
        int r = rr + HL, c = cc + HL;
        int gy = gy0 + r, gx = gx0 + c;
        float px_c = spx[r*TPS+c];
        float px_l = spx[r*TPS+c-1];
        float dx = (gx == 0) ? px_c : ((gx == HN-1) ? -px_l : px_c - px_l);
        float py_c = spy[r*TPS+c];
        float py_u = spy[(r-1)*TPS+c];
        float dy = (gy == 0) ? py_c : ((gy == HN-1) ? -py_u : py_c - py_u);
        O[gy*HN + gx] = sx[r*TPS+c] - LAM_TV * (dx + dy);
    }
}

// ---------------- warp-parallel 3-level Haar + soft-threshold + FISTA ----------------
__device__ __forceinline__ float softt(float v) {
    float m = fabsf(v) - LAM_W;
    return (m > 0.f) ? copysignf(m, v) : 0.f;
}

__global__ void __launch_bounds__(256) k_wav(const float* __restrict__ xtv,
                                             const float* __restrict__ xold,
                                             float* __restrict__ xnew,
                                             float* __restrict__ znew,
                                             float coef, int plane0) {
    const unsigned FM = 0xffffffffu;
    const float s = INV_S2;
    int gw = (blockIdx.x * 256 + threadIdx.x) >> 5;
    int lane = threadIdx.x & 31;
    int plane = plane0 + gw / 400;
    int rem = gw % 400;
    int rowblk = rem / 10, colgrp = rem - rowblk*10;
    int r = lane >> 2, b = lane & 3;
    int base = plane*NPLANE + (rowblk*8 + r)*HN + colgrp*32 + b*8;

    float a[8];
    {
        float4 v0 = *(const float4*)(xtv + base);
        float4 v1 = *(const float4*)(xtv + base + 4);
        a[0]=v0.x; a[1]=v0.y; a[2]=v0.z; a[3]=v0.w;
        a[4]=v1.x; a[5]=v1.y; a[6]=v1.z; a[7]=v1.w;
    }
    // forward level 1
    {
        float t[8];
#pragma unroll
        for (int j = 0; j < 4; j++) { t[j] = (a[2*j]+a[2*j+1])*s; t[j+4] = (a[2*j]-a[2*j+1])*s; }
#pragma unroll
        for (int j = 0; j < 8; j++) a[j] = t[j];
        int rr = r & 3;
        int s0 = (2*rr)*4 + b, s1 = s0 + 4;
        float sg = (r < 4) ? 1.f : -1.f;
#pragma unroll
        for (int j = 0; j < 8; j++) {
            float u0 = __shfl_sync(FM, a[j], s0);
            float u1 = __shfl_sync(FM, a[j], s1);
            a[j] = (u0 + sg*u1) * s;
        }
#pragma unroll
        for (int j = 0; j < 8; j++) if (r >= 4 || j >= 4) a[j] = softt(a[j]);
    }
    // forward level 2
    {
        if (r < 4) {
            float t0=(a[0]+a[1])*s, t1=(a[2]+a[3])*s, t2=(a[0]-a[1])*s, t3=(a[2]-a[3])*s;
            a[0]=t0; a[1]=t1; a[2]=t2; a[3]=t3;
        }
        int rr = r & 1;
        int s0 = (2*rr)*4 + b, s1 = s0 + 4;
        float sg = (r < 2) ? 1.f : -1.f;
#pragma unroll
        for (int j = 0; j < 4; j++) {
            float u0 = __shfl_sync(FM, a[j], s0);
            float u1 = __shfl_sync(FM, a[j], s1);
            if (r < 4) a[j] = (u0 + sg*u1) * s;
        }
#pragma unroll
        for (int j = 0; j < 4; j++) if (r < 4 && (r >= 2 || j >= 2)) a[j] = softt(a[j]);
    }
    // forward level 3
    {
        if (r < 2) {
            float t0=(a[0]+a[1])*s, t1=(a[0]-a[1])*s;
            a[0]=t0; a[1]=t1;
        }
        int s0 = b, s1 = 4 + b;
        float sg = (r == 0) ? 1.f : -1.f;
#pragma unroll
        for (int j = 0; j < 2; j++) {
            float u0 = __shfl_sync(FM, a[j], s0);
            float u1 = __shfl_sync(FM, a[j], s1);
            if (r < 2) a[j] = (u0 + sg*u1) * s;
        }
        if (r == 1) a[0] = softt(a[0]);
        if (r < 2)  a[1] = softt(a[1]);
    }
    // inverse level 3
    {
        int s0 = b, s1 = 4 + b;
        float sg = (r & 1) ? -1.f : 1.f;
#pragma unroll
        for (int j = 0; j < 2; j++) {
            float u0 = __shfl_sync(FM, a[j], s0);
            float u1 = __shfl_sync(FM, a[j], s1);
            if (r < 2) a[j] = (u0 + sg*u1) * s;
        }
        if (r < 2) {
            float t0=(a[0]+a[1])*s, t1=(a[0]-a[1])*s;
            a[0]=t0; a[1]=t1;
        }
    }
    // inverse level 2
    {
        int pj = (r >> 1) & 1;
        int s0 = pj*4 + b, s1 = (pj+2)*4 + b;
        float sg = (r & 1) ? -1.f : 1.f;
#pragma unroll
        for (int j = 0; j < 4; j++) {
            float u0 = __shfl_sync(FM, a[j], s0);
            float u1 = __shfl_sync(FM, a[j], s1);
            if (r < 4) a[j] = (u0 + sg*u1) * s;
        }
        if (r < 4) {
            float t0=(a[0]+a[2])*s, t1=(a[0]-a[2])*s, t2=(a[1]+a[3])*s, t3=(a[1]-a[3])*s;
            a[0]=t0; a[1]=t1; a[2]=t2; a[3]=t3;
        }
    }
    // inverse level 1
    {
        int pj = r >> 1;
        int s0 = pj*4 + b, s1 = (pj+4)*4 + b;
        float sg = (r & 1) ? -1.f : 1.f;
#pragma unroll
        for (int j = 0; j < 8; j++) {
            float u0 = __shfl_sync(FM, a[j], s0);
            float u1 = __shfl_sync(FM, a[j], s1);
            a[j] = (u0 + sg*u1) * s;
        }
        float t[8];
#pragma unroll
        for (int j = 0; j < 4; j++) { t[2*j] = (a[j]+a[j+4])*s; t[2*j+1] = (a[j]-a[j+4])*s; }
#pragma unroll
        for (int j = 0; j < 8; j++) a[j] = t[j];
    }
    // FISTA epilogue
    {
        float4 xo0 = *(const float4*)(xold + base);
        float4 xo1 = *(const float4*)(xold + base + 4);
        float xov[8] = {xo0.x,xo0.y,xo0.z,xo0.w,xo1.x,xo1.y,xo1.z,xo1.w};
        float xn[8], zn[8];
#pragma unroll
        for (int j = 0; j < 8; j++) {
            float v = a[j];
            xn[j] = v;
            zn[j] = v + coef*(v - xov[j]);
        }
        *(float4*)(xnew + base)     = make_float4(xn[0],xn[1],xn[2],xn[3]);
        *(float4*)(xnew + base + 4) = make_float4(xn[4],xn[5],xn[6],xn[7]);
        *(float4*)(znew + base)     = make_float4(zn[0],zn[1],zn[2],zn[3]);
        *(float4*)(znew + base + 4) = make_float4(zn[4],zn[5],zn[6],zn[7]);
    }
}

// ---------------- host ----------------
extern "C" void kernel_launch(void* const* d_in, const int* in_sizes, int n_in,
                              void* d_out, int out_size) {
    (void)in_sizes; (void)n_in; (void)out_size;
    const float* y = (const float*)d_in[0];
    const float* mask = (const float*)d_in[1];
    float* out = (float*)d_out;

    float *Z, *X, *T1, *T2;
    float2 *T1c, *T2c;
    cudaGetSymbolAddress((void**)&Z,   g_Z);
    cudaGetSymbolAddress((void**)&X,   g_X);
    cudaGetSymbolAddress((void**)&T1,  g_T1);
    cudaGetSymbolAddress((void**)&T2,  g_T2);
    cudaGetSymbolAddress((void**)&T1c, g_T1c);
    cudaGetSymbolAddress((void**)&T2c, g_T2c);

    cudaFuncSetAttribute(k_tv, cudaFuncAttributeMaxDynamicSharedMemorySize, TVSMEM);

    // one-time stream/event setup (host objects, created on the first
    // (non-capturing) correctness call; reused identically thereafter)
    static bool inited = false;
    static cudaStream_t st[NCH-1];
    static cudaEvent_t evFork, evJoin[NCH-1];
    if (!inited) {
        for (int i = 0; i < NCH-1; i++)
            cudaStreamCreateWithFlags(&st[i], cudaStreamNonBlocking);
        cudaEventCreateWithFlags(&evFork, cudaEventDisableTiming);
        for (int i = 0; i < NCH-1; i++)
            cudaEventCreateWithFlags(&evJoin[i], cudaEventDisableTiming);
        inited = true;
    }

    float coefs[15];
    {
        double t = 1.0;
        for (int k = 0; k < 15; k++) {
            double tn = (1.0 + sqrt(1.0 + 4.0*t*t)) / 2.0;
            coefs[k] = (float)((t - 1.0) / tn);
            t = tn;
        }
    }

    // init (full batch, default stream)
    k_tw<<<1, 320>>>();
    k_prep<<<1600, 256>>>(y, mask);
    k_fft_p2c<<<FGRID, FTH>>>(y, T1c, -1.f, 1.0f, 0);
    k_fft_c2p<<<FGRID, FTH>>>(T1c, X, Z, -1.f, 1.f/320.f, 0);

    // fork
    cudaEventRecord(evFork, 0);
    for (int i = 0; i < NCH-1; i++) cudaStreamWaitEvent(st[i], evFork, 0);

    // 4 independent image chains
    for (int g = 0; g < NCH; g++) {
        cudaStream_t sg = (g == 0) ? (cudaStream_t)0 : st[g-1];
        int img0 = g * IPC;
        int plane0 = img0 * 2;
        for (int it = 0; it < 15; it++) {
            k_fft_p2c<<<FG2, FTH, 0, sg>>>(Z, T1c, 1.f, 1.f/320.f, img0);
            k_fft_mid<<<FG2, FTH, 0, sg>>>(T1c, T2c, img0);
            k_fft_last<<<FG2, FTH, 0, sg>>>(T2c, Z, T1, img0);
            k_tv<<<IPC*2*25, TVTH, TVSMEM, sg>>>(T1, T2, plane0);
            float* xnew = (it == 14) ? out : X;
            k_wav<<<IPC*2*50, 256, 0, sg>>>(T2, X, xnew, Z, coefs[it], plane0);
        }
    }

    // join
    for (int i = 0; i < NCH-1; i++) {
        cudaEventRecord(evJoin[i], st[i]);
        cudaStreamWaitEvent((cudaStream_t)0, evJoin[i], 0);
    }
}